// round 7
// baseline (speedup 1.0000x reference)
#include <cuda_runtime.h>
#include <cstdint>

// MeshConv: g = 5 symmetric features of x[...,0:5]; y = conv1x5(g, W) + b
// x: (4,16,500000,5) f32   W: (16,16,1,5) f32   b: (16,)   y: (4,16,5,499996) f32
//
// f32x2 lanes packed over (co, co+1); g operand {g,g} dup'd from scalar smem.
// R6 change: 10-warp CTA (TILE=256) to fix SMSP imbalance of the 5-warp block
// (wid%4 -> (2,1,1,1) load). Now (3,3,2,2) per CTA, (6,6,4,4) at 2 CTAs/SM.

#define F_DIM  500000
#define FO     499996
#define CI_N   16
#define CO_N   16
#define N_B    4
#define TILE   256
#define GR     260            // TILE + 4 halo
#define NTHR   320            // 10 warps: w>>1 = h, w&1 = fg-half; lane: cg, fg_lo

typedef unsigned long long ull;

__device__ __forceinline__ void fma2(ull &d, ull a, ull b) {
    asm("fma.rn.f32x2 %0, %1, %2, %0;" : "+l"(d) : "l"(a), "l"(b));
}
__device__ __forceinline__ ull pack2(float lo, float hi) {
    ull r; asm("mov.b64 %0, {%1, %2};" : "=l"(r) : "f"(lo), "f"(hi)); return r;
}
__device__ __forceinline__ float2 unpack2(ull v) {
    float2 r; asm("mov.b64 {%0, %1}, %2;" : "=f"(r.x), "=f"(r.y) : "l"(v)); return r;
}
__device__ __forceinline__ void lds128u(ull &a, ull &b, uint32_t addr) {
    asm("ld.shared.v2.u64 {%0, %1}, [%2];" : "=l"(a), "=l"(b) : "r"(addr));
}
__device__ __forceinline__ float4 lds128f(uint32_t addr) {
    float4 v;
    asm("ld.shared.v4.f32 {%0, %1, %2, %3}, [%4];"
        : "=f"(v.x), "=f"(v.y), "=f"(v.z), "=f"(v.w) : "r"(addr));
    return v;
}

// smem: g [ci][h][GR] f32 = 16*5*260*4 = 83200B ; W = 640 ull = 5120B
#define G_FLOATS (CI_N*5*GR)
#define W_ULL    (CI_N*2*5*4)
#define SMEM_BYTES (G_FLOATS*4 + W_ULL*8)

extern __shared__ float smem_dyn[];

__global__ __launch_bounds__(NTHR, 2)
void meshconv_kernel(const float* __restrict__ x, const float* __restrict__ W,
                     const float* __restrict__ b, float* __restrict__ y)
{
    float* gsh  = smem_dyn;
    ull*   wdsh = (ull*)(smem_dyn + G_FLOATS);

    const int tid = threadIdx.x;
    const int n   = blockIdx.y;
    const int f0  = blockIdx.x * TILE;

    // ---- pack W into smem: wdsh[((ci*2+cg)*5+k)*4+j] = {W(c0), W(c0+1)}, c0=cg*8+2j ----
    for (int idx = tid; idx < W_ULL; idx += NTHR) {
        int j  = idx & 3;
        int t  = idx >> 2;
        int k  = t % 5;
        int u  = t / 5;
        int cg = u & 1;
        int ci = u >> 1;
        int c0 = cg*8 + 2*j;
        wdsh[idx] = pack2(W[(c0*CI_N + ci)*5 + k], W[((c0+1)*CI_N + ci)*5 + k]);
    }

    // ---- build g tile (scalar floats, x read once) ----
    for (int id = tid; id < CI_N*GR; id += NTHR) {
        int ci = id / GR;
        int r  = id % GR;
        int f  = f0 + r;
        float v0 = 0.f, v1 = 0.f, v2 = 0.f, v3 = 0.f, v4 = 0.f;
        if (f < F_DIM) {
            const float* xp = x + ((size_t)(n*CI_N + ci)*F_DIM + f)*5;
            v0 = xp[0]; v1 = xp[1]; v2 = xp[2]; v3 = xp[3]; v4 = xp[4];
        }
        float* gp = gsh + ci*5*GR;
        gp[0*GR + r] = v0;
        gp[1*GR + r] = v1 + v3;
        gp[2*GR + r] = v2 + v4;
        gp[3*GR + r] = fabsf(v1 - v3);
        gp[4*GR + r] = fabsf(v2 - v4);
    }
    __syncthreads();

    // ---- compute: warp w -> (h = w>>1, fhalf = w&1); lane -> (cg, fg_lo) ----
    const int w    = tid >> 5;        // 0..9
    const int h    = w >> 1;          // 0..4 (warp-uniform)
    const int fh   = w & 1;           // 0..1
    const int lane = tid & 31;
    const int cg   = lane >> 4;       // 0..1
    const int fg   = fh*16 + (lane & 15);   // 0..31 -> 8 consecutive f each
    const int co0  = cg * 8;

    uint32_t gaddr = (uint32_t)__cvta_generic_to_shared(gsh + h*GR + fg*8);
    uint32_t waddr = (uint32_t)__cvta_generic_to_shared(wdsh + cg*20);

    ull acc[8][4];
    #pragma unroll
    for (int j = 0; j < 4; ++j) {
        ull bp = pack2(b[co0 + 2*j], b[co0 + 2*j + 1]);
        #pragma unroll
        for (int p = 0; p < 8; ++p) acc[p][j] = bp;
    }

    #pragma unroll 1
    for (int ci = 0; ci < CI_N; ++ci) {
        float4 va = lds128f(gaddr);
        float4 vb = lds128f(gaddr + 16);
        float4 vc = lds128f(gaddr + 32);
        ull gd[12];
        gd[0]  = pack2(va.x, va.x);  gd[1]  = pack2(va.y, va.y);
        gd[2]  = pack2(va.z, va.z);  gd[3]  = pack2(va.w, va.w);
        gd[4]  = pack2(vb.x, vb.x);  gd[5]  = pack2(vb.y, vb.y);
        gd[6]  = pack2(vb.z, vb.z);  gd[7]  = pack2(vb.w, vb.w);
        gd[8]  = pack2(vc.x, vc.x);  gd[9]  = pack2(vc.y, vc.y);
        gd[10] = pack2(vc.z, vc.z);  gd[11] = pack2(vc.w, vc.w);

        #pragma unroll
        for (int k = 0; k < 5; ++k) {
            ull w0, w1, w2, w3;                        // 4 co-pairs for tap k
            lds128u(w0, w1, waddr + k*32);
            lds128u(w2, w3, waddr + k*32 + 16);
            #pragma unroll
            for (int p = 0; p < 8; ++p) {
                fma2(acc[p][0], gd[p+k], w0);
                fma2(acc[p][1], gd[p+k], w1);
                fma2(acc[p][2], gd[p+k], w2);
                fma2(acc[p][3], gd[p+k], w3);
            }
        }
        gaddr += 5*GR*4;       // next ci in g
        waddr += 40*8;         // next ci in W (40 ull)
    }

    // ---- store: per co-pair, unpack into per-co float4 runs (coalesced) ----
    const int f = f0 + fg*8;
    #pragma unroll
    for (int j = 0; j < 4; ++j) {
        const int c = co0 + 2*j;
        float* ylo = y + ((size_t)((n*CO_N + c)*5 + h))*FO + f;
        float* yhi = ylo + (size_t)5*FO;               // co+1 row

        float2 a0 = unpack2(acc[0][j]), a1 = unpack2(acc[1][j]);
        float2 a2 = unpack2(acc[2][j]), a3 = unpack2(acc[3][j]);
        float2 a4 = unpack2(acc[4][j]), a5 = unpack2(acc[5][j]);
        float2 a6 = unpack2(acc[6][j]), a7 = unpack2(acc[7][j]);

        if (f < FO) {                                  // FO%4==0, f%8==0 -> quad safe
            *(float4*)ylo = make_float4(a0.x, a1.x, a2.x, a3.x);
            *(float4*)yhi = make_float4(a0.y, a1.y, a2.y, a3.y);
        }
        if (f + 4 < FO) {
            *(float4*)(ylo + 4) = make_float4(a4.x, a5.x, a6.x, a7.x);
            *(float4*)(yhi + 4) = make_float4(a4.y, a5.y, a6.y, a7.y);
        }
    }
}

extern "C" void kernel_launch(void* const* d_in, const int* in_sizes, int n_in,
                              void* d_out, int out_size)
{
    (void)in_sizes; (void)n_in; (void)out_size;
    const float* x = (const float*)d_in[0];
    const float* W = (const float*)d_in[1];
    const float* b = (const float*)d_in[2];
    float*       y = (float*)d_out;

    cudaFuncSetAttribute(meshconv_kernel,
                         cudaFuncAttributeMaxDynamicSharedMemorySize, SMEM_BYTES);

    dim3 grid((FO + TILE - 1) / TILE, N_B);
    meshconv_kernel<<<grid, NTHR, SMEM_BYTES>>>(x, W, b, y);
}

// round 10
// speedup vs baseline: 1.3129x; 1.3129x over previous
#include <cuda_runtime.h>
#include <cuda_bf16.h>
#include <cstdint>

// MeshConv via mma.sync (HMMA) split-bf16 GEMM.
// y[n,co,h,f] = sum_{ci,k} g[n,ci,h,f+k]*W[co,ci,k] + b[co]
// Per (n,h,ftile): D[128f,16co] = A[f,p]·B[p,co], p=(k_tap,ci), K=80.
// Split: g=ghi+glo, W=whi+wlo; D = Ahi·Bhi + Alo·Bhi + Ahi·Blo (lo·lo dropped).

#define F_DIM  500000
#define FO     499996
#define NTILES 3907
#define NTHR   256
#define GR     132
#define ROWB   48                 // bytes per g row (16 ci bf16, padded 32->48 for banks)
#define PLANE  (GR*ROWB)          // 6336 B per (h)
#define GOFF   (5*PLANE)          // 31680 B per {hi,lo} plane set
#define SMEM_BYTES (2*GOFF)       // 63360 B

typedef unsigned int u32;

__device__ __forceinline__ void mma16816(float* c, const u32* a, const u32* b) {
    asm volatile("mma.sync.aligned.m16n8k16.row.col.f32.bf16.bf16.f32 "
        "{%0,%1,%2,%3}, {%4,%5,%6,%7}, {%8,%9}, {%0,%1,%2,%3};"
        : "+f"(c[0]), "+f"(c[1]), "+f"(c[2]), "+f"(c[3])
        : "r"(a[0]), "r"(a[1]), "r"(a[2]), "r"(a[3]), "r"(b[0]), "r"(b[1]));
}
__device__ __forceinline__ unsigned short bfu(float v) {
    return __bfloat16_as_ushort(__float2bfloat16(v));
}

extern __shared__ unsigned char smem[];

__global__ __launch_bounds__(NTHR, 2)
void meshconv_mma(const float* __restrict__ x, const float* __restrict__ W,
                  const float* __restrict__ b, float* __restrict__ y)
{
    const int tid  = threadIdx.x;
    const int wid  = tid >> 5, lane = tid & 31;
    const int grp  = lane >> 2, tg = lane & 3;
    const int n    = blockIdx.y;
    const int f0   = blockIdx.x * 128;

    // ---- B fragments in registers (built once): pairs over adjacent ci ----
    // b-frag (col-major B, k x n = 16 x 8): lane holds col = grp, k = tg*2(+1) [j=0], +8 [j=1]
    u32 bhi[5][2][2], blo[5][2][2];
    float bias[2][2];
    #pragma unroll
    for (int nt = 0; nt < 2; ++nt) {
        #pragma unroll
        for (int p = 0; p < 2; ++p) bias[nt][p] = __ldg(b + nt*8 + tg*2 + p);
    }
    #pragma unroll
    for (int s = 0; s < 5; ++s)
        #pragma unroll
        for (int nt = 0; nt < 2; ++nt)
            #pragma unroll
            for (int j = 0; j < 2; ++j) {
                int co = nt*8 + grp;
                int ci = tg*2 + j*8;
                float w0 = __ldg(W + (co*16 + ci    )*5 + s);
                float w1 = __ldg(W + (co*16 + ci + 1)*5 + s);
                __nv_bfloat16 h0 = __float2bfloat16(w0), h1 = __float2bfloat16(w1);
                float l0 = w0 - __bfloat162float(h0), l1 = w1 - __bfloat162float(h1);
                bhi[s][nt][j] = (u32)__bfloat16_as_ushort(h0) | ((u32)__bfloat16_as_ushort(h1) << 16);
                blo[s][nt][j] = (u32)bfu(l0) | ((u32)bfu(l1) << 16);
            }

    // ---- gpack build: x -> ghi/glo bf16 planes [sel][h][r][ci], row stride 48B ----
    for (int u = tid; u < GR*8; u += NTHR) {
        int r = u >> 3, cp = u & 7;
        int f = f0 + r;
        float v0[5], v1[5];
        if (f < F_DIM) {
            const float* x0 = x + ((size_t)(n*16 + cp*2)*F_DIM + f)*5;
            const float* x1 = x0 + (size_t)5*F_DIM;
            #pragma unroll
            for (int k = 0; k < 5; ++k) { v0[k] = x0[k]; v1[k] = x1[k]; }
        } else {
            #pragma unroll
            for (int k = 0; k < 5; ++k) { v0[k] = 0.f; v1[k] = 0.f; }
        }
        float g0[5], g1[5];
        g0[0]=v0[0]; g0[1]=v0[1]+v0[3]; g0[2]=v0[2]+v0[4];
        g0[3]=fabsf(v0[1]-v0[3]); g0[4]=fabsf(v0[2]-v0[4]);
        g1[0]=v1[0]; g1[1]=v1[1]+v1[3]; g1[2]=v1[2]+v1[4];
        g1[3]=fabsf(v1[1]-v1[3]); g1[4]=fabsf(v1[2]-v1[4]);
        #pragma unroll
        for (int h = 0; h < 5; ++h) {
            __nv_bfloat16 h0 = __float2bfloat16(g0[h]), h1 = __float2bfloat16(g1[h]);
            float l0 = g0[h] - __bfloat162float(h0), l1 = g1[h] - __bfloat162float(h1);
            u32 ph = (u32)__bfloat16_as_ushort(h0) | ((u32)__bfloat16_as_ushort(h1) << 16);
            u32 pl = (u32)bfu(l0) | ((u32)bfu(l1) << 16);
            u32 off = (u32)((h*GR + r)*ROWB + cp*4);
            *(u32*)(smem + off)        = ph;
            *(u32*)(smem + GOFF + off) = pl;
        }
    }
    __syncthreads();

    // ---- compute: warp = m-tile (16 rows), both n8 tiles, loop h ----
    const int mt = wid;
    // A-frag lane addresses: row = mt*16 + grp (+8), ci pair = tg*2 (+8)
    const u32 abase = (u32)((mt*16 + grp)*ROWB + tg*4);

    #pragma unroll 1
    for (int h = 0; h < 5; ++h) {
        float acc[2][4];
        #pragma unroll
        for (int nt = 0; nt < 2; ++nt) {
            acc[nt][0] = bias[nt][0]; acc[nt][1] = bias[nt][1];
            acc[nt][2] = bias[nt][0]; acc[nt][3] = bias[nt][1];
        }

        u32 ahi[5][4];
        // pass 1: Ahi x Bhi  (keep Ahi frags live for pass 3)
        #pragma unroll
        for (int s = 0; s < 5; ++s) {
            const u32* ap = (const u32*)(smem + h*PLANE + abase + s*ROWB);
            ahi[s][0] = ap[0];  ahi[s][1] = ap[96];     // +8 rows = 96 words
            ahi[s][2] = ap[4];  ahi[s][3] = ap[100];    // ci+8 = +16B = 4 words
            mma16816(acc[0], ahi[s], bhi[s][0]);
            mma16816(acc[1], ahi[s], bhi[s][1]);
        }
        // pass 2: Alo x Bhi
        #pragma unroll
        for (int s = 0; s < 5; ++s) {
            const u32* ap = (const u32*)(smem + GOFF + h*PLANE + abase + s*ROWB);
            u32 alo[4];
            alo[0] = ap[0]; alo[1] = ap[96]; alo[2] = ap[4]; alo[3] = ap[100];
            mma16816(acc[0], alo, bhi[s][0]);
            mma16816(acc[1], alo, bhi[s][1]);
        }
        // pass 3: Ahi x Blo
        #pragma unroll
        for (int s = 0; s < 5; ++s) {
            mma16816(acc[0], ahi[s], blo[s][0]);
            mma16816(acc[1], ahi[s], blo[s][1]);
        }

        // ---- store: c0/c1 at row fr, c2/c3 at fr+8; cols co0, co0+1 ----
        const int fr = f0 + mt*16 + grp;
        #pragma unroll
        for (int nt = 0; nt < 2; ++nt) {
            const int co0 = nt*8 + tg*2;
            float* y0 = y + ((size_t)((n*16 + co0)*5 + h))*FO;
            float* y1 = y0 + (size_t)5*FO;
            if (fr < FO)     { y0[fr]   = acc[nt][0];  y1[fr]   = acc[nt][1]; }
            if (fr + 8 < FO) { y0[fr+8] = acc[nt][2];  y1[fr+8] = acc[nt][3]; }
        }
    }
}

extern "C" void kernel_launch(void* const* d_in, const int* in_sizes, int n_in,
                              void* d_out, int out_size)
{
    (void)in_sizes; (void)n_in; (void)out_size;
    const float* x = (const float*)d_in[0];
    const float* W = (const float*)d_in[1];
    const float* b = (const float*)d_in[2];
    float*       y = (float*)d_out;

    cudaFuncSetAttribute(meshconv_mma,
                         cudaFuncAttributeMaxDynamicSharedMemorySize, SMEM_BYTES);

    dim3 grid(NTILES, 4);
    meshconv_mma<<<grid, NTHR, SMEM_BYTES>>>(x, W, b, y);
}

// round 11
// speedup vs baseline: 1.5754x; 1.2000x over previous
#include <cuda_runtime.h>
#include <cuda_fp16.h>
#include <cstdint>

// MeshConv via mma.sync (HMMA) fp16 GEMM, split on B only.
// y[n,co,h,f] = sum_{ci,k} g[n,ci,h,f+k]*W[co,ci,k] + b[co]
// Per (n,h,ftile): D[128f,16co] = A[f,p]·B[p,co], p=(k_tap,ci), K=80.
// A = fp16(g) single plane (err 2^-11 -> rel ~2e-4); B = Whi + Wlo fp16 (exact-ish).
// D = A·Bhi + A·Blo, A-fragments loaded once per h and reused across both passes.

#define F_DIM  500000
#define FO     499996
#define NTILES 3907
#define NTHR   256
#define GR     132
#define ROWB   48                 // bytes per g row (8 ci-pair words, padded 32->48)
#define PLANE  (GR*ROWB)          // 6336 B per h
#define SMEM_BYTES (5*PLANE)      // 31680 B

typedef unsigned int u32;

__device__ __forceinline__ void mma16816(float* c, const u32* a, const u32* b) {
    asm volatile("mma.sync.aligned.m16n8k16.row.col.f32.f16.f16.f32 "
        "{%0,%1,%2,%3}, {%4,%5,%6,%7}, {%8,%9}, {%0,%1,%2,%3};"
        : "+f"(c[0]), "+f"(c[1]), "+f"(c[2]), "+f"(c[3])
        : "r"(a[0]), "r"(a[1]), "r"(a[2]), "r"(a[3]), "r"(b[0]), "r"(b[1]));
}
__device__ __forceinline__ u32 packh(float a, float bq) {   // {lo=a, hi=bq}
    return (u32)__half_as_ushort(__float2half(a))
         | ((u32)__half_as_ushort(__float2half(bq)) << 16);
}

extern __shared__ unsigned char smem[];

__global__ __launch_bounds__(NTHR, 2)
void meshconv_mma(const float* __restrict__ x, const float* __restrict__ W,
                  const float* __restrict__ b, float* __restrict__ y)
{
    const int tid  = threadIdx.x;
    const int wid  = tid >> 5, lane = tid & 31;
    const int grp  = lane >> 2, tg = lane & 3;
    const int n    = blockIdx.y;
    const int f0   = blockIdx.x * 128;

    // ---- B fragments in registers: W split into fp16 hi+lo ----
    // b-frag (col-major, 16k x 8n): lane = col grp; j=0: k=tg*2,tg*2+1; j=1: +8
    u32 bhi[5][2][2], blo[5][2][2];
    float bias[2][2];
    #pragma unroll
    for (int nt = 0; nt < 2; ++nt)
        #pragma unroll
        for (int p = 0; p < 2; ++p) bias[nt][p] = __ldg(b + nt*8 + tg*2 + p);
    #pragma unroll
    for (int s = 0; s < 5; ++s)
        #pragma unroll
        for (int nt = 0; nt < 2; ++nt)
            #pragma unroll
            for (int j = 0; j < 2; ++j) {
                int co = nt*8 + grp;
                int ci = tg*2 + j*8;
                float w0 = __ldg(W + (co*16 + ci    )*5 + s);
                float w1 = __ldg(W + (co*16 + ci + 1)*5 + s);
                __half h0 = __float2half(w0), h1 = __float2half(w1);
                float l0 = w0 - __half2float(h0), l1 = w1 - __half2float(h1);
                bhi[s][nt][j] = (u32)__half_as_ushort(h0) | ((u32)__half_as_ushort(h1) << 16);
                blo[s][nt][j] = packh(l0, l1);
            }

    // ---- gpack build: x -> fp16 plane [h][r][ci-pair], row stride 48B ----
    // warp mapping 8r x 4cp (banks 12r+cp distinct mod 32 -> 1 wf per STS)
    for (int u = tid; u < 1088; u += NTHR) {
        int r_lo = u & 7, cp_lo = (u >> 3) & 3, q = u >> 5;
        int cp = cp_lo + 4*(q & 1);
        int r  = r_lo + 8*(q >> 1);
        if (r >= GR) continue;
        int f = f0 + r;
        float v0[5], v1[5];
        if (f < F_DIM) {
            const float* x0 = x + ((size_t)(n*16 + cp*2)*F_DIM + f)*5;
            const float* x1 = x0 + (size_t)5*F_DIM;
            #pragma unroll
            for (int k = 0; k < 5; ++k) { v0[k] = x0[k]; v1[k] = x1[k]; }
        } else {
            #pragma unroll
            for (int k = 0; k < 5; ++k) { v0[k] = 0.f; v1[k] = 0.f; }
        }
        float g0[5], g1[5];
        g0[0]=v0[0]; g0[1]=v0[1]+v0[3]; g0[2]=v0[2]+v0[4];
        g0[3]=fabsf(v0[1]-v0[3]); g0[4]=fabsf(v0[2]-v0[4]);
        g1[0]=v1[0]; g1[1]=v1[1]+v1[3]; g1[2]=v1[2]+v1[4];
        g1[3]=fabsf(v1[1]-v1[3]); g1[4]=fabsf(v1[2]-v1[4]);
        #pragma unroll
        for (int h = 0; h < 5; ++h)
            *(u32*)(smem + (h*GR + r)*ROWB + cp*4) = packh(g0[h], g1[h]);
    }
    __syncthreads();

    // ---- compute: warp = m-tile (16 rows), 2 n-tiles, loop h ----
    const int mt = wid;
    const u32 abase = (u32)((mt*16 + grp)*ROWB + tg*4);

    #pragma unroll 1
    for (int h = 0; h < 5; ++h) {
        float acc[2][4];
        #pragma unroll
        for (int nt = 0; nt < 2; ++nt) {
            acc[nt][0] = bias[nt][0]; acc[nt][1] = bias[nt][1];
            acc[nt][2] = bias[nt][0]; acc[nt][3] = bias[nt][1];
        }

        u32 af[5][4];
        // pass 1: A x Bhi (A frags stay live)
        #pragma unroll
        for (int s = 0; s < 5; ++s) {
            const u32* ap = (const u32*)(smem + h*PLANE + abase + s*ROWB);
            af[s][0] = ap[0];  af[s][1] = ap[96];     // +8 rows = 384B = 96 words
            af[s][2] = ap[4];  af[s][3] = ap[100];    // ci+8 = +16B
            mma16816(acc[0], af[s], bhi[s][0]);
            mma16816(acc[1], af[s], bhi[s][1]);
        }
        // pass 2: A x Blo
        #pragma unroll
        for (int s = 0; s < 5; ++s) {
            mma16816(acc[0], af[s], blo[s][0]);
            mma16816(acc[1], af[s], blo[s][1]);
        }

        // ---- store: c0/c1 at row fr, c2/c3 at fr+8; cols co0, co0+1 ----
        const int fr = f0 + mt*16 + grp;
        #pragma unroll
        for (int nt = 0; nt < 2; ++nt) {
            const int co0 = nt*8 + tg*2;
            float* y0 = y + ((size_t)((n*16 + co0)*5 + h))*FO;
            float* y1 = y0 + (size_t)5*FO;
            if (fr < FO)     { y0[fr]   = acc[nt][0];  y1[fr]   = acc[nt][1]; }
            if (fr + 8 < FO) { y0[fr+8] = acc[nt][2];  y1[fr+8] = acc[nt][3]; }
        }
    }
}

extern "C" void kernel_launch(void* const* d_in, const int* in_sizes, int n_in,
                              void* d_out, int out_size)
{
    (void)in_sizes; (void)n_in; (void)out_size;
    const float* x = (const float*)d_in[0];
    const float* W = (const float*)d_in[1];
    const float* b = (const float*)d_in[2];
    float*       y = (float*)d_out;

    cudaFuncSetAttribute(meshconv_mma,
                         cudaFuncAttributeMaxDynamicSharedMemorySize, SMEM_BYTES);

    dim3 grid(NTILES, 4);
    meshconv_mma<<<grid, NTHR, SMEM_BYTES>>>(x, W, b, y);
}

// round 12
// speedup vs baseline: 1.9174x; 1.2171x over previous
#include <cuda_runtime.h>
#include <cuda_fp16.h>
#include <cstdint>

// MeshConv via mma.sync (HMMA) fp16 GEMM, split on B only.
// Per (n,h,ftile): D[256f,16co] = A[f,p]·B[p,co], p=(k_tap,ci), K=80.
// A = fp16(g); B = Whi + Wlo fp16. D = A·Bhi + A·Blo.
// R11: 256-f tile, warp = 2 m-tiles x 2 n-tiles = 4 independent MMA chains (ILP).

#define F_DIM  500000
#define FO     499996
#define TILE_F 256
#define NTILES 1954
#define NTHR   256
#define GR     260                // TILE_F + 4 halo
#define ROWB   48                 // bytes per g row (8 ci-pair words, padded 32->48)
#define PLANE  (GR*ROWB)          // 12480 B per h
#define SMEM_BYTES (5*PLANE)      // 62400 B

typedef unsigned int u32;

__device__ __forceinline__ void mma16816(float* c, const u32* a, const u32* b) {
    asm volatile("mma.sync.aligned.m16n8k16.row.col.f32.f16.f16.f32 "
        "{%0,%1,%2,%3}, {%4,%5,%6,%7}, {%8,%9}, {%0,%1,%2,%3};"
        : "+f"(c[0]), "+f"(c[1]), "+f"(c[2]), "+f"(c[3])
        : "r"(a[0]), "r"(a[1]), "r"(a[2]), "r"(a[3]), "r"(b[0]), "r"(b[1]));
}
__device__ __forceinline__ u32 packh(float a, float bq) {   // {lo=a, hi=bq}
    return (u32)__half_as_ushort(__float2half(a))
         | ((u32)__half_as_ushort(__float2half(bq)) << 16);
}

extern __shared__ unsigned char smem[];

__global__ __launch_bounds__(NTHR, 2)
void meshconv_mma(const float* __restrict__ x, const float* __restrict__ W,
                  const float* __restrict__ b, float* __restrict__ y)
{
    const int tid  = threadIdx.x;
    const int wid  = tid >> 5, lane = tid & 31;
    const int grp  = lane >> 2, tg = lane & 3;
    const int n    = blockIdx.y;
    const int f0   = blockIdx.x * TILE_F;

    // ---- B fragments in registers: W split into fp16 hi+lo ----
    u32 bhi[5][2][2], blo[5][2][2];
    float bias[2][2];
    #pragma unroll
    for (int nt = 0; nt < 2; ++nt)
        #pragma unroll
        for (int p = 0; p < 2; ++p) bias[nt][p] = __ldg(b + nt*8 + tg*2 + p);
    #pragma unroll
    for (int s = 0; s < 5; ++s)
        #pragma unroll
        for (int nt = 0; nt < 2; ++nt)
            #pragma unroll
            for (int j = 0; j < 2; ++j) {
                int co = nt*8 + grp;
                int ci = tg*2 + j*8;
                float w0 = __ldg(W + (co*16 + ci    )*5 + s);
                float w1 = __ldg(W + (co*16 + ci + 1)*5 + s);
                __half h0 = __float2half(w0), h1 = __float2half(w1);
                float l0 = w0 - __half2float(h0), l1 = w1 - __half2float(h1);
                bhi[s][nt][j] = (u32)__half_as_ushort(h0) | ((u32)__half_as_ushort(h1) << 16);
                blo[s][nt][j] = packh(l0, l1);
            }

    // ---- gpack build: x -> fp16 plane [h][r][ci-pair], row stride 48B ----
    // bank-friendly warp mapping 8r x 4cp (banks 12r+cp distinct -> 1 wf per STS)
    for (int u = tid; u < 2112; u += NTHR) {
        int r_lo = u & 7, cp_lo = (u >> 3) & 3, q = u >> 5;
        int cp = cp_lo + 4*(q & 1);
        int r  = r_lo + 8*(q >> 1);
        if (r >= GR) continue;
        int f = f0 + r;
        float v0[5], v1[5];
        if (f < F_DIM) {
            const float* x0 = x + ((size_t)(n*16 + cp*2)*F_DIM + f)*5;
            const float* x1 = x0 + (size_t)5*F_DIM;
            #pragma unroll
            for (int k = 0; k < 5; ++k) { v0[k] = x0[k]; v1[k] = x1[k]; }
        } else {
            #pragma unroll
            for (int k = 0; k < 5; ++k) { v0[k] = 0.f; v1[k] = 0.f; }
        }
        float g0[5], g1[5];
        g0[0]=v0[0]; g0[1]=v0[1]+v0[3]; g0[2]=v0[2]+v0[4];
        g0[3]=fabsf(v0[1]-v0[3]); g0[4]=fabsf(v0[2]-v0[4]);
        g1[0]=v1[0]; g1[1]=v1[1]+v1[3]; g1[2]=v1[2]+v1[4];
        g1[3]=fabsf(v1[1]-v1[3]); g1[4]=fabsf(v1[2]-v1[4]);
        #pragma unroll
        for (int h = 0; h < 5; ++h)
            *(u32*)(smem + (h*GR + r)*ROWB + cp*4) = packh(g0[h], g1[h]);
    }
    __syncthreads();

    // ---- compute: warp = rows [wid*32, wid*32+32) = 2 m-tiles, 2 n-tiles each ----
    const u32 abase0 = (u32)((wid*32      + grp)*ROWB + tg*4);
    const u32 abase1 = (u32)((wid*32 + 16 + grp)*ROWB + tg*4);

    #pragma unroll 1
    for (int h = 0; h < 5; ++h) {
        float acc[2][2][4];                       // [m][nt][c]
        #pragma unroll
        for (int m = 0; m < 2; ++m)
            #pragma unroll
            for (int nt = 0; nt < 2; ++nt) {
                acc[m][nt][0] = bias[nt][0]; acc[m][nt][1] = bias[nt][1];
                acc[m][nt][2] = bias[nt][0]; acc[m][nt][3] = bias[nt][1];
            }

        u32 af0[5][4], af1[5][4];
        // pass 1: A x Bhi  (A frags stay live for pass 2)
        #pragma unroll
        for (int s = 0; s < 5; ++s) {
            const u32* a0 = (const u32*)(smem + h*PLANE + abase0 + s*ROWB);
            const u32* a1 = (const u32*)(smem + h*PLANE + abase1 + s*ROWB);
            af0[s][0] = a0[0];  af0[s][1] = a0[96];   // +8 rows = 384B
            af0[s][2] = a0[4];  af0[s][3] = a0[100];  // ci+8 = +16B
            af1[s][0] = a1[0];  af1[s][1] = a1[96];
            af1[s][2] = a1[4];  af1[s][3] = a1[100];
            mma16816(acc[0][0], af0[s], bhi[s][0]);
            mma16816(acc[0][1], af0[s], bhi[s][1]);
            mma16816(acc[1][0], af1[s], bhi[s][0]);
            mma16816(acc[1][1], af1[s], bhi[s][1]);
        }
        // pass 2: A x Blo
        #pragma unroll
        for (int s = 0; s < 5; ++s) {
            mma16816(acc[0][0], af0[s], blo[s][0]);
            mma16816(acc[0][1], af0[s], blo[s][1]);
            mma16816(acc[1][0], af1[s], blo[s][0]);
            mma16816(acc[1][1], af1[s], blo[s][1]);
        }

        // ---- store ----
        #pragma unroll
        for (int m = 0; m < 2; ++m) {
            const int fr = f0 + wid*32 + m*16 + grp;
            #pragma unroll
            for (int nt = 0; nt < 2; ++nt) {
                const int co0 = nt*8 + tg*2;
                float* y0 = y + ((size_t)((n*16 + co0)*5 + h))*FO;
                float* y1 = y0 + (size_t)5*FO;
                if (fr < FO)     { y0[fr]   = acc[m][nt][0];  y1[fr]   = acc[m][nt][1]; }
                if (fr + 8 < FO) { y0[fr+8] = acc[m][nt][2];  y1[fr+8] = acc[m][nt][3]; }
            }
        }
    }
}

extern "C" void kernel_launch(void* const* d_in, const int* in_sizes, int n_in,
                              void* d_out, int out_size)
{
    (void)in_sizes; (void)n_in; (void)out_size;
    const float* x = (const float*)d_in[0];
    const float* W = (const float*)d_in[1];
    const float* b = (const float*)d_in[2];
    float*       y = (float*)d_out;

    cudaFuncSetAttribute(meshconv_mma,
                         cudaFuncAttributeMaxDynamicSharedMemorySize, SMEM_BYTES);

    dim3 grid(NTILES, 4);
    meshconv_mma<<<grid, NTHR, SMEM_BYTES>>>(x, W, b, y);
}

// round 13
// speedup vs baseline: 2.2577x; 1.1775x over previous
#include <cuda_runtime.h>
#include <cuda_fp16.h>
#include <cstdint>

// MeshConv via mma.sync (HMMA) fp16, split on B (W = Whi + Wlo), A = fp16(g).
// R12: 3 CTAs/SM (24 warps) via register diet:
//  - A-frags via ldmatrix.x4 (transient), loaded once per (m,s), used for hi+lo
//  - B-frags prepacked per-lane in smem, one LDS.128 per (s,nt) covers hi+lo
//  - fused hi/lo pass per tap s (4 chains, same-acc spacing 4)

#define F_DIM  500000
#define FO     499996
#define TILE_F 256
#define NTILES 1954
#define NTHR   256
#define GR     260                // TILE_F + 4 halo
#define ROWB   48                 // g row bytes (8 ci-pair words, padded 32->48)
#define PLANE  (GR*ROWB)          // 12480 B per h
#define OFF_B  (5*PLANE)          // 62400
#define SMEM_BYTES (OFF_B + 5120) // + B table 5s*2nt*32lane*16B

typedef unsigned int u32;

__device__ __forceinline__ void mma16816(float* c, const u32* a, u32 b0, u32 b1) {
    asm volatile("mma.sync.aligned.m16n8k16.row.col.f32.f16.f16.f32 "
        "{%0,%1,%2,%3}, {%4,%5,%6,%7}, {%8,%9}, {%0,%1,%2,%3};"
        : "+f"(c[0]), "+f"(c[1]), "+f"(c[2]), "+f"(c[3])
        : "r"(a[0]), "r"(a[1]), "r"(a[2]), "r"(a[3]), "r"(b0), "r"(b1));
}
__device__ __forceinline__ void ldmx4(u32* r, u32 addr) {
    asm volatile("ldmatrix.sync.aligned.m8n8.x4.shared.b16 {%0,%1,%2,%3}, [%4];"
        : "=r"(r[0]), "=r"(r[1]), "=r"(r[2]), "=r"(r[3]) : "r"(addr));
}
__device__ __forceinline__ void lds128(u32* r, u32 addr) {
    asm volatile("ld.shared.v4.b32 {%0,%1,%2,%3}, [%4];"
        : "=r"(r[0]), "=r"(r[1]), "=r"(r[2]), "=r"(r[3]) : "r"(addr));
}
__device__ __forceinline__ u32 packh(float a, float bq) {   // {lo=a, hi=bq}
    return (u32)__half_as_ushort(__float2half(a))
         | ((u32)__half_as_ushort(__float2half(bq)) << 16);
}

extern __shared__ unsigned char smem[];

__global__ __launch_bounds__(NTHR, 3)
void meshconv_mma(const float* __restrict__ x, const float* __restrict__ W,
                  const float* __restrict__ b, float* __restrict__ y)
{
    const int tid  = threadIdx.x;
    const int wid  = tid >> 5, lane = tid & 31;
    const int grp  = lane >> 2, tg = lane & 3;
    const int n    = blockIdx.y;
    const int f0   = blockIdx.x * TILE_F;
    const u32 sbase = (u32)__cvta_generic_to_shared(smem);

    // ---- B table build: entry (s,nt,lane) = {bhi_j0, bhi_j1, blo_j0, blo_j1} ----
    for (int u = tid; u < 320; u += NTHR) {
        int el = u & 31, nt = (u >> 5) & 1, s = u >> 6;
        int egrp = el >> 2, etg = el & 3;
        int co = nt*8 + egrp;
        u32 e[4];
        #pragma unroll
        for (int j = 0; j < 2; ++j) {
            int ci = etg*2 + j*8;
            float w0 = __ldg(W + (co*16 + ci    )*5 + s);
            float w1 = __ldg(W + (co*16 + ci + 1)*5 + s);
            __half h0 = __float2half(w0), h1 = __float2half(w1);
            e[j]   = (u32)__half_as_ushort(h0) | ((u32)__half_as_ushort(h1) << 16);
            e[2+j] = packh(w0 - __half2float(h0), w1 - __half2float(h1));
        }
        asm volatile("st.shared.v4.b32 [%0], {%1,%2,%3,%4};"
            :: "r"(sbase + OFF_B + (u32)u*16), "r"(e[0]), "r"(e[1]), "r"(e[2]), "r"(e[3])
            : "memory");
    }

    // ---- gpack build: x -> fp16 plane [h][r][ci-pair], row stride 48B ----
    for (int u = tid; u < 2112; u += NTHR) {
        int r_lo = u & 7, cp_lo = (u >> 3) & 3, q = u >> 5;
        int cp = cp_lo + 4*(q & 1);
        int r  = r_lo + 8*(q >> 1);
        if (r >= GR) continue;
        int f = f0 + r;
        float v0[5], v1[5];
        if (f < F_DIM) {
            const float* x0 = x + ((size_t)(n*16 + cp*2)*F_DIM + f)*5;
            const float* x1 = x0 + (size_t)5*F_DIM;
            #pragma unroll
            for (int k = 0; k < 5; ++k) { v0[k] = x0[k]; v1[k] = x1[k]; }
        } else {
            #pragma unroll
            for (int k = 0; k < 5; ++k) { v0[k] = 0.f; v1[k] = 0.f; }
        }
        float g0[5], g1[5];
        g0[0]=v0[0]; g0[1]=v0[1]+v0[3]; g0[2]=v0[2]+v0[4];
        g0[3]=fabsf(v0[1]-v0[3]); g0[4]=fabsf(v0[2]-v0[4]);
        g1[0]=v1[0]; g1[1]=v1[1]+v1[3]; g1[2]=v1[2]+v1[4];
        g1[3]=fabsf(v1[1]-v1[3]); g1[4]=fabsf(v1[2]-v1[4]);
        #pragma unroll
        for (int h = 0; h < 5; ++h)
            *(u32*)(smem + (h*GR + r)*ROWB + cp*4) = packh(g0[h], g1[h]);
    }
    __syncthreads();

    // ---- per-lane ldmatrix offset: mat = lane>>3 -> {rowoff, colbyte} ----
    const int matid = lane >> 3, r8 = lane & 7;
    const u32 laneoff = (u32)((r8 + ((matid & 1) << 3)) * ROWB + ((matid >> 1) << 4));
    const u32 am0 = sbase + (u32)(wid*32)*ROWB + laneoff;         // m-tile 0 rows
    const u32 am1 = am0 + 16*ROWB;                                 // m-tile 1
    const u32 bbase = sbase + OFF_B + (u32)lane*16;

    float bias0 = __ldg(b + tg*2), bias1 = __ldg(b + tg*2 + 1);
    float bias2 = __ldg(b + 8 + tg*2), bias3 = __ldg(b + 8 + tg*2 + 1);

    #pragma unroll 1
    for (int h = 0; h < 5; ++h) {
        float acc[2][2][4];                       // [m][nt][c]
        #pragma unroll
        for (int m = 0; m < 2; ++m) {
            acc[m][0][0]=bias0; acc[m][0][1]=bias1; acc[m][0][2]=bias0; acc[m][0][3]=bias1;
            acc[m][1][0]=bias2; acc[m][1][1]=bias3; acc[m][1][2]=bias2; acc[m][1][3]=bias3;
        }
        const u32 hb = (u32)(h*PLANE);

        #pragma unroll
        for (int s = 0; s < 5; ++s) {
            u32 a0[4], a1[4], e0[4], e1[4];
            ldmx4(a0, am0 + hb + (u32)s*ROWB);
            ldmx4(a1, am1 + hb + (u32)s*ROWB);
            lds128(e0, bbase + (u32)(s*2    )*512);
            lds128(e1, bbase + (u32)(s*2 + 1)*512);
            mma16816(acc[0][0], a0, e0[0], e0[1]);   // hi
            mma16816(acc[0][1], a0, e1[0], e1[1]);
            mma16816(acc[1][0], a1, e0[0], e0[1]);
            mma16816(acc[1][1], a1, e1[0], e1[1]);
            mma16816(acc[0][0], a0, e0[2], e0[3]);   // lo
            mma16816(acc[0][1], a0, e1[2], e1[3]);
            mma16816(acc[1][0], a1, e0[2], e0[3]);
            mma16816(acc[1][1], a1, e1[2], e1[3]);
        }

        // ---- store ----
        #pragma unroll
        for (int m = 0; m < 2; ++m) {
            const int fr = f0 + wid*32 + m*16 + grp;
            #pragma unroll
            for (int nt = 0; nt < 2; ++nt) {
                const int co0 = nt*8 + tg*2;
                float* y0 = y + ((size_t)((n*16 + co0)*5 + h))*FO;
                float* y1 = y0 + (size_t)5*FO;
                if (fr < FO)     { y0[fr]   = acc[m][nt][0];  y1[fr]   = acc[m][nt][1]; }
                if (fr + 8 < FO) { y0[fr+8] = acc[m][nt][2];  y1[fr+8] = acc[m][nt][3]; }
            }
        }
    }
}

extern "C" void kernel_launch(void* const* d_in, const int* in_sizes, int n_in,
                              void* d_out, int out_size)
{
    (void)in_sizes; (void)n_in; (void)out_size;
    const float* x = (const float*)d_in[0];
    const float* W = (const float*)d_in[1];
    const float* b = (const float*)d_in[2];
    float*       y = (float*)d_out;

    cudaFuncSetAttribute(meshconv_mma,
                         cudaFuncAttributeMaxDynamicSharedMemorySize, SMEM_BYTES);

    dim3 grid(NTILES, 4);
    meshconv_mma<<<grid, NTHR, SMEM_BYTES>>>(x, W, b, y);
}

// round 15
// speedup vs baseline: 2.3945x; 1.0606x over previous
#include <cuda_runtime.h>
#include <cuda_fp16.h>
#include <cstdint>

// MeshConv via mma.sync (HMMA) fp16, split on B (W = Whi + Wlo), A = fp16(g).
// R13: cp.async coalesced x staging -> smem raw buffer -> bank-perfect 5-float
// LDS -> gpack. Kills the 20B-stride LDG wavefront waste (46% of L1 work).
// TILE_F=128, 128 thr (4 warps, SMSP-balanced), 5 CTAs/SM.

#define F_DIM  500000
#define FO     499996
#define TILE_F 128
#define NTILES 3907
#define NTHR   128
#define GR     132
#define ROWB   48                 // gpack row bytes (8 ci-pair words + pad)
#define PLANE  (GR*ROWB)          // 6336 B per h
#define OFF_RAW (5*PLANE)         // 31680: raw x staging / B table overlay
#define RAWSTR 2656               // raw plane stride (2640 + 16 pad, bank-tuned)
#define SMEM_BYTES (OFF_RAW + 4*RAWSTR)   // 42304

typedef unsigned int u32;

__device__ __forceinline__ void mma16816(float* c, const u32* a, u32 b0, u32 b1) {
    asm volatile("mma.sync.aligned.m16n8k16.row.col.f32.f16.f16.f32 "
        "{%0,%1,%2,%3}, {%4,%5,%6,%7}, {%8,%9}, {%0,%1,%2,%3};"
        : "+f"(c[0]), "+f"(c[1]), "+f"(c[2]), "+f"(c[3])
        : "r"(a[0]), "r"(a[1]), "r"(a[2]), "r"(a[3]), "r"(b0), "r"(b1));
}
__device__ __forceinline__ void ldmx4(u32* r, u32 addr) {
    asm volatile("ldmatrix.sync.aligned.m8n8.x4.shared.b16 {%0,%1,%2,%3}, [%4];"
        : "=r"(r[0]), "=r"(r[1]), "=r"(r[2]), "=r"(r[3]) : "r"(addr));
}
__device__ __forceinline__ void lds128(u32* r, u32 addr) {
    asm volatile("ld.shared.v4.b32 {%0,%1,%2,%3}, [%4];"
        : "=r"(r[0]), "=r"(r[1]), "=r"(r[2]), "=r"(r[3]) : "r"(addr));
}
__device__ __forceinline__ u32 packh(float a, float bq) {   // {lo=a, hi=bq}
    return (u32)__half_as_ushort(__float2half(a))
         | ((u32)__half_as_ushort(__float2half(bq)) << 16);
}

extern __shared__ unsigned char smem[];

__global__ __launch_bounds__(NTHR, 5)
void meshconv_mma(const float* __restrict__ x, const float* __restrict__ W,
                  const float* __restrict__ b, float* __restrict__ y)
{
    const int tid  = threadIdx.x;
    const int wid  = tid >> 5, lane = tid & 31;
    const int grp  = lane >> 2, tg = lane & 3;
    const int n    = blockIdx.y;
    const int f0   = blockIdx.x * TILE_F;
    const u32 sbase = (u32)__cvta_generic_to_shared(smem);

    // valid bytes in a 2640B ci-slice starting at f0 (tail zero-filled)
    long long vbl = ((long long)F_DIM - f0) * 20;
    int vb = vbl > GR*20 ? GR*20 : (int)vbl;

    const char* xb = (const char*)x;

    // ==== staging + gpack build, 4 chunks of 4 ci planes ====
    for (int c = 0; c < 4; ++c) {
        // coalesced 16B cp.async of 4 ci slices into raw buffer
        for (int i = tid; i < 660; i += NTHR) {
            int p  = i / 165, o = i - p*165;
            int ob = o * 16;
            int sz = vb - ob; sz = sz < 0 ? 0 : (sz > 16 ? 16 : sz);
            const char* src = xb + ((size_t)((n*16 + 4*c + p))*F_DIM + f0)*20 + (sz ? ob : 0);
            u32 dst = sbase + OFF_RAW + p*RAWSTR + ob;
            asm volatile("cp.async.ca.shared.global [%0], [%1], 16, %2;"
                         :: "r"(dst), "l"(src), "r"(sz) : "memory");
        }
        asm volatile("cp.async.commit_group;" ::: "memory");
        asm volatile("cp.async.wait_group 0;" ::: "memory");
        __syncthreads();

        // g-compute: thread = (r, ci-pair within chunk); bank-perfect raw LDS
        {
            const int rl = lane & 15, cpl = lane >> 4;
            const int cp = 2*c + cpl;
            for (int rb = wid*16; rb < GR; rb += 64) {
                int r = rb + rl;
                if (r < GR) {
                    const float* pa = (const float*)(smem + OFF_RAW + (2*cpl  )*RAWSTR + r*20);
                    const float* pb = (const float*)(smem + OFF_RAW + (2*cpl+1)*RAWSTR + r*20);
                    float a0=pa[0], a1=pa[1], a2=pa[2], a3=pa[3], a4=pa[4];
                    float c0=pb[0], c1=pb[1], c2=pb[2], c3=pb[3], c4=pb[4];
                    float gA[5], gB[5];
                    gA[0]=a0; gA[1]=a1+a3; gA[2]=a2+a4; gA[3]=fabsf(a1-a3); gA[4]=fabsf(a2-a4);
                    gB[0]=c0; gB[1]=c1+c3; gB[2]=c2+c4; gB[3]=fabsf(c1-c3); gB[4]=fabsf(c2-c4);
                    #pragma unroll
                    for (int h = 0; h < 5; ++h)
                        *(u32*)(smem + h*PLANE + r*ROWB + cp*4) = packh(gA[h], gB[h]);
                }
            }
        }
        __syncthreads();
    }

    // ==== B table rebuild (overlays raw buffer): {bhi0,bhi1,blo0,blo1}/lane ====
    for (int u = tid; u < 320; u += NTHR) {
        int el = u & 31, nt = (u >> 5) & 1, s = u >> 6;
        int egrp = el >> 2, etg = el & 3;
        int co = nt*8 + egrp;
        u32 e[4];
        #pragma unroll
        for (int j = 0; j < 2; ++j) {
            int ci = etg*2 + j*8;
            float w0 = __ldg(W + (co*16 + ci    )*5 + s);
            float w1 = __ldg(W + (co*16 + ci + 1)*5 + s);
            __half h0 = __float2half(w0), h1 = __float2half(w1);
            e[j]   = (u32)__half_as_ushort(h0) | ((u32)__half_as_ushort(h1) << 16);
            e[2+j] = packh(w0 - __half2float(h0), w1 - __half2float(h1));
        }
        asm volatile("st.shared.v4.b32 [%0], {%1,%2,%3,%4};"
            :: "r"(sbase + OFF_RAW + (u32)u*16), "r"(e[0]), "r"(e[1]), "r"(e[2]), "r"(e[3])
            : "memory");
    }
    __syncthreads();

    // ==== mma phase (identical structure to R12; 4 warps x 32 rows) ====
    const int matid = lane >> 3, r8 = lane & 7;
    const u32 laneoff = (u32)((r8 + ((matid & 1) << 3)) * ROWB + ((matid >> 1) << 4));
    const u32 am0 = sbase + (u32)(wid*32)*ROWB + laneoff;
    const u32 am1 = am0 + 16*ROWB;
    const u32 bbase = sbase + OFF_RAW + (u32)lane*16;

    float bias0 = __ldg(b + tg*2), bias1 = __ldg(b + tg*2 + 1);
    float bias2 = __ldg(b + 8 + tg*2), bias3 = __ldg(b + 8 + tg*2 + 1);

    #pragma unroll 1
    for (int h = 0; h < 5; ++h) {
        float acc[2][2][4];                       // [m][nt][c]
        #pragma unroll
        for (int m = 0; m < 2; ++m) {
            acc[m][0][0]=bias0; acc[m][0][1]=bias1; acc[m][0][2]=bias0; acc[m][0][3]=bias1;
            acc[m][1][0]=bias2; acc[m][1][1]=bias3; acc[m][1][2]=bias2; acc[m][1][3]=bias3;
        }
        const u32 hb = (u32)(h*PLANE);

        #pragma unroll
        for (int s = 0; s < 5; ++s) {
            u32 a0[4], a1[4], e0[4], e1[4];
            ldmx4(a0, am0 + hb + (u32)s*ROWB);
            ldmx4(a1, am1 + hb + (u32)s*ROWB);
            lds128(e0, bbase + (u32)(s*2    )*512);
            lds128(e1, bbase + (u32)(s*2 + 1)*512);
            mma16816(acc[0][0], a0, e0[0], e0[1]);   // hi
            mma16816(acc[0][1], a0, e1[0], e1[1]);
            mma16816(acc[1][0], a1, e0[0], e0[1]);
            mma16816(acc[1][1], a1, e1[0], e1[1]);
            mma16816(acc[0][0], a0, e0[2], e0[3]);   // lo
            mma16816(acc[0][1], a0, e1[2], e1[3]);
            mma16816(acc[1][0], a1, e0[2], e0[3]);
            mma16816(acc[1][1], a1, e1[2], e1[3]);
        }

        // ---- store ----
        #pragma unroll
        for (int m = 0; m < 2; ++m) {
            const int fr = f0 + wid*32 + m*16 + grp;
            #pragma unroll
            for (int nt = 0; nt < 2; ++nt) {
                const int co0 = nt*8 + tg*2;
                float* y0 = y + ((size_t)((n*16 + co0)*5 + h))*FO;
                float* y1 = y0 + (size_t)5*FO;
                if (fr < FO)     { y0[fr]   = acc[m][nt][0];  y1[fr]   = acc[m][nt][1]; }
                if (fr + 8 < FO) { y0[fr+8] = acc[m][nt][2];  y1[fr+8] = acc[m][nt][3]; }
            }
        }
    }
}

extern "C" void kernel_launch(void* const* d_in, const int* in_sizes, int n_in,
                              void* d_out, int out_size)
{
    (void)in_sizes; (void)n_in; (void)out_size;
    const float* x = (const float*)d_in[0];
    const float* W = (const float*)d_in[1];
    const float* b = (const float*)d_in[2];
    float*       y = (float*)d_out;

    cudaFuncSetAttribute(meshconv_mma,
                         cudaFuncAttributeMaxDynamicSharedMemorySize, SMEM_BYTES);

    dim3 grid(NTILES, 4);
    meshconv_mma<<<grid, NTHR, SMEM_BYTES>>>(x, W, b, y);
}